// round 4
// baseline (speedup 1.0000x reference)
#include <cuda_runtime.h>
#include <stdint.h>

#define NUM_CLASSES 10000
#define FEATURE_DIM 2048
#define BATCH 512
#define TPB 256
#define NTOT ((size_t)NUM_CLASSES * FEATURE_DIM)   // 20,480,000 floats
#define COPY_GRID (148 * 8)
// ALPHA = 0.5 exactly -> powers of two via ldexpf

__device__ int g_lab[BATCH];          // decoded labels
__device__ int g_cnt[NUM_CLASSES];    // per-class occurrence count
__device__ int g_work[BATCH];         // distinct labels worklist
__device__ int g_nwork;               // number of distinct labels

// ---------------------------------------------------------------------------
// Prep: zero loss, zero touched counts, decode labels (int64 vs int32 probe),
// histogram, build distinct-label worklist. One block, 512 threads.
// Counts are zeroed LAST-launch-safe: only counts of touched labels are ever
// nonzero, and we re-zero exactly those from the previous decode? No — counts
// for all classes zeroed via worklist-free full sweep is 10000/512 ~ 20 iters,
// trivial. Keep the full sweep for determinism.
// ---------------------------------------------------------------------------
__global__ void prep_kernel(const int* __restrict__ labels_words,
                            float* __restrict__ loss_out) {
    __shared__ int s_not64;
    int tid = threadIdx.x;
    if (tid == 0) { s_not64 = 0; g_nwork = 0; loss_out[0] = 0.0f; }
    for (int i = tid; i < NUM_CLASSES; i += BATCH) g_cnt[i] = 0;
    __syncthreads();
    int lo = labels_words[2 * tid];
    int hi = labels_words[2 * tid + 1];
    // int64 hypothesis: every odd word 0, every even word a valid class id.
    if (hi != 0 || lo < 0 || lo >= NUM_CLASSES) s_not64 = 1;   // benign race
    __syncthreads();
    int lab = s_not64 ? labels_words[tid] : lo;
    g_lab[tid] = lab;
    int prev = atomicAdd(&g_cnt[lab], 1);
    if (prev == 0) {                       // first occurrence -> worklist
        int p = atomicAdd(&g_nwork, 1);
        g_work[p] = lab;
    }
}

// ---------------------------------------------------------------------------
// Flat streaming copy: centers -> out_centers (all rows; matched rows are
// overwritten by the fixup kernel afterwards).
// MODE 0: dst 16B-aligned   -> pure float4 grid-stride copy
// MODE 1: dst ≡ 4 (mod 16)  -> output quads at dst+3+4t are 16B-aligned;
//                              each is {src[4t+3], S_{t+1}.xyz} built from one
//                              aligned LDG.128 + one aligned LDG.32.
// MODE 2: fallback scalar.
// ---------------------------------------------------------------------------
template <int MODE>
__global__ void __launch_bounds__(TPB)
copy_kernel(const float* __restrict__ src, float* __restrict__ dst) {
    const size_t gid    = (size_t)blockIdx.x * TPB + threadIdx.x;
    const size_t stride = (size_t)COPY_GRID * TPB;

    if (MODE == 0) {
        const float4* s4 = (const float4*)src;
        float4*       d4 = (float4*)dst;
        const size_t  T  = NTOT / 4;
        #pragma unroll 4
        for (size_t t = gid; t < T; t += stride)
            __stcs(d4 + t, __ldcs(s4 + t));
    } else if (MODE == 1) {
        if (gid == 0) {
            dst[0] = src[0]; dst[1] = src[1]; dst[2] = src[2];
            dst[NTOT - 1] = src[NTOT - 1];
        }
        const float4* s4 = (const float4*)src;          // 16B aligned
        const size_t  T  = NTOT / 4 - 1;                // quads t = 0..T-1
        #pragma unroll 4
        for (size_t t = gid; t < T; t += stride) {
            float4 q = __ldcs(s4 + t + 1);
            float  w = __ldcs(src + 4 * t + 3);         // L1-hit (line touched)
            __stcs((float4*)(dst + 3 + 4 * t), make_float4(w, q.x, q.y, q.z));
        }
    } else {
        #pragma unroll 8
        for (size_t t = gid; t < NTOT; t += stride)
            __stcs(dst + t, __ldcs(src + t));
    }
}

// ---------------------------------------------------------------------------
// Fixup: one block per distinct label. Recompute that row with the closed-form
// sequential EMA  new_c = 2^-k * c + sum_r 2^-(k-r) * f_r  (batch order,
// ALPHA=0.5) and accumulate the full MSE loss (all k samples of this class,
// against the ORIGINAL center row).
// ---------------------------------------------------------------------------
__global__ void __launch_bounds__(TPB)
fixup_kernel(const float* __restrict__ features,
             const float* __restrict__ centers,
             float* __restrict__ out_centers,
             float* __restrict__ loss_out) {
    __shared__ int   s_match[BATCH];
    __shared__ float s_w[BATCH];
    __shared__ int   s_cnt;
    __shared__ float s_red[TPB / 32];

    if (blockIdx.x >= (unsigned)g_nwork) return;
    const int l   = g_work[blockIdx.x];
    const int tid = threadIdx.x;
    const int k   = g_cnt[l];

    if (tid == 0) s_cnt = 0;
    __syncthreads();
    for (int j = tid; j < BATCH; j += TPB) {
        if (g_lab[j] == l) {
            int p = atomicAdd(&s_cnt, 1);
            s_match[p] = j;
        }
    }
    __syncthreads();

    if (tid == 0) {   // restore batch order; precompute EMA weights
        for (int a = 1; a < k; a++) {
            int v = s_match[a];
            int b = a - 1;
            while (b >= 0 && s_match[b] > v) { s_match[b + 1] = s_match[b]; b--; }
            s_match[b + 1] = v;
        }
        for (int r = 0; r < k; r++) s_w[r] = ldexpf(1.0f, -(k - r));
    }
    __syncthreads();

    const float* crow = centers     + (size_t)l * FEATURE_DIM;
    float*       orow = out_centers + (size_t)l * FEATURE_DIM;
    const float  decay = ldexpf(1.0f, -k);
    float acc = 0.0f;

    #pragma unroll
    for (int s = 0; s < FEATURE_DIM / TPB; s++) {
        int c = tid + s * TPB;
        float cv = __ldg(crow + c);
        float nv = cv * decay;
        for (int r = 0; r < k; r++) {
            float f = __ldg(features + (size_t)s_match[r] * FEATURE_DIM + c);
            nv = fmaf(s_w[r], f, nv);
            float d = f - cv;             // loss uses ORIGINAL center row
            acc = fmaf(d, d, acc);
        }
        orow[c] = nv;
    }

    #pragma unroll
    for (int o = 16; o; o >>= 1) acc += __shfl_xor_sync(0xffffffffu, acc, o);
    if ((tid & 31) == 0) s_red[tid >> 5] = acc;
    __syncthreads();
    if (tid < TPB / 32) {
        acc = s_red[tid];
        #pragma unroll
        for (int o = (TPB / 64); o; o >>= 1)
            acc += __shfl_xor_sync((1u << (TPB / 32)) - 1u, acc, o);
        if (tid == 0)
            atomicAdd(loss_out, acc * (1.0f / ((float)BATCH * (float)FEATURE_DIM)));
    }
}

extern "C" void kernel_launch(void* const* d_in, const int* in_sizes, int n_in,
                              void* d_out, int out_size) {
    const float* features = (const float*)d_in[0];
    const int*   labels_w = (const int*)d_in[1];
    const float* centers  = (const float*)d_in[2];

    float* out = (float*)d_out;
    float* out_centers = out + ((size_t)out_size - NTOT);

    prep_kernel<<<1, BATCH>>>(labels_w, out);

    uintptr_t a = (uintptr_t)out_centers;
    if ((a & 15) == 0)
        copy_kernel<0><<<COPY_GRID, TPB>>>(centers, out_centers);
    else if ((a & 15) == 4)
        copy_kernel<1><<<COPY_GRID, TPB>>>(centers, out_centers);
    else
        copy_kernel<2><<<COPY_GRID, TPB>>>(centers, out_centers);

    fixup_kernel<<<BATCH, TPB>>>(features, centers, out_centers, out);
}